// round 2
// baseline (speedup 1.0000x reference)
#include <cuda_runtime.h>

// ConstantCurrentLIFEncoder: 100 steps of LIF dynamics with constant input.
//   v' = v + 0.1f * ((0 - v) + I)
//   z  = (v' - 1.0f > 0) ? 1 : 0
//   v  = v' - z * (v' - 0)
// Input:  [64, 8192] f32 (524288 elems)
// Output: [100, 64, 8192] f32 spikes (52428800 elems)
//
// Pure DRAM-write-bound (210 MB out). Grid 1024x128 = exactly one thread per
// float4 lane, 6.92 CTAs/SM (vs 3.46 with 512x256) -> ~1% wave imbalance
// instead of 15%.

#define N_ELEMS   524288
#define N_VEC     (N_ELEMS / 4)   // 131072 float4 lanes
#define SEQ_LEN   100

__global__ void __launch_bounds__(128)
lif_encoder_kernel(const float* __restrict__ in, float* __restrict__ out) {
    const int idx = blockIdx.x * blockDim.x + threadIdx.x;   // exact cover, no bounds check needed
    const float4 I = __ldg(reinterpret_cast<const float4*>(in) + idx);

    float vx = 0.0f, vy = 0.0f, vz = 0.0f, vw = 0.0f;

    float4* o = reinterpret_cast<float4*>(out) + idx;

    #pragma unroll 10
    for (int t = 0; t < SEQ_LEN; t++) {
        // integrate (match reference op order: dv = 0.1 * ((0 - v) + I); v += dv)
        vx = vx + 0.1f * ((0.0f - vx) + I.x);
        vy = vy + 0.1f * ((0.0f - vy) + I.y);
        vz = vz + 0.1f * ((0.0f - vz) + I.z);
        vw = vw + 0.1f * ((0.0f - vw) + I.w);

        float4 s;
        s.x = (vx - 1.0f > 0.0f) ? 1.0f : 0.0f;
        s.y = (vy - 1.0f > 0.0f) ? 1.0f : 0.0f;
        s.z = (vz - 1.0f > 0.0f) ? 1.0f : 0.0f;
        s.w = (vw - 1.0f > 0.0f) ? 1.0f : 0.0f;

        // reset: v = v - z * (v - 0)
        vx = vx - s.x * vx;
        vy = vy - s.y * vy;
        vz = vz - s.z * vz;
        vw = vw - s.w * vw;

        // streaming store: output (210 MB) has no reuse, bypass L2 persistence
        __stcs(o + (size_t)t * N_VEC, s);
    }
}

extern "C" void kernel_launch(void* const* d_in, const int* in_sizes, int n_in,
                              void* d_out, int out_size) {
    const float* in = (const float*)d_in[0];
    float* out = (float*)d_out;

    // 1024 blocks x 128 threads = 131072 threads = one per float4 lane.
    lif_encoder_kernel<<<1024, 128>>>(in, out);
}

// round 3
// speedup vs baseline: 1.3602x; 1.3602x over previous
#include <cuda_runtime.h>

// ConstantCurrentLIFEncoder: 100 steps of LIF dynamics with constant input.
//   v' = v + 0.1f * ((0 - v) + I)
//   z  = (v' - 1.0f > 0) ? 1 : 0
//   v  = v' - z * (v' - 0)
// Input:  [64, 8192] f32 (524288 elems)
// Output: [100, 64, 8192] f32 spikes (52428800 elems)
//
// Pure DRAM-write-bound (210 MB out). Strategy: 2-way time-split.
// Grid = 1024 x 256: blocks [0,512) handle t=0..49, blocks [512,1024)
// recompute the cheap recurrence warm-up (t=0..49, no stores) and store
// t=50..99. Doubles warps/SM (~23 -> ~55) => doubles outstanding-store MLP,
// at negligible redundant-FMA cost (fma pipe was only 15% busy).

#define N_ELEMS   524288
#define N_VEC     (N_ELEMS / 4)   // 131072 float4 lanes
#define SEQ_LEN   100
#define T_HALF    50
#define BLOCKS_PER_HALF 512       // 512 * 256 threads = 131072 lanes

__global__ void __launch_bounds__(256)
lif_encoder_kernel(const float* __restrict__ in, float* __restrict__ out) {
    const int half = blockIdx.x >> 9;                       // 0 or 1
    const int idx  = ((blockIdx.x & 511) << 8) + threadIdx.x;  // float4 lane

    const float4 I = __ldg(reinterpret_cast<const float4*>(in) + idx);

    float vx = 0.0f, vy = 0.0f, vz = 0.0f, vw = 0.0f;

    // Warm-up for the second half: advance the recurrence t=0..49, no stores.
    // (Spike reset included for bit-exact state; compute pipe is nearly idle.)
    if (half) {
        #pragma unroll 5
        for (int t = 0; t < T_HALF; t++) {
            vx = vx + 0.1f * ((0.0f - vx) + I.x);
            vy = vy + 0.1f * ((0.0f - vy) + I.y);
            vz = vz + 0.1f * ((0.0f - vz) + I.z);
            vw = vw + 0.1f * ((0.0f - vw) + I.w);
            float sx = (vx - 1.0f > 0.0f) ? 1.0f : 0.0f;
            float sy = (vy - 1.0f > 0.0f) ? 1.0f : 0.0f;
            float sz = (vz - 1.0f > 0.0f) ? 1.0f : 0.0f;
            float sw = (vw - 1.0f > 0.0f) ? 1.0f : 0.0f;
            vx = vx - sx * vx;
            vy = vy - sy * vy;
            vz = vz - sz * vz;
            vw = vw - sw * vw;
        }
    }

    // Store phase: 50 timesteps, one coalesced STG.128 each.
    float4* o = reinterpret_cast<float4*>(out) + (size_t)(half * T_HALF) * N_VEC + idx;

    #pragma unroll 5
    for (int t = 0; t < T_HALF; t++) {
        vx = vx + 0.1f * ((0.0f - vx) + I.x);
        vy = vy + 0.1f * ((0.0f - vy) + I.y);
        vz = vz + 0.1f * ((0.0f - vz) + I.z);
        vw = vw + 0.1f * ((0.0f - vw) + I.w);

        float4 s;
        s.x = (vx - 1.0f > 0.0f) ? 1.0f : 0.0f;
        s.y = (vy - 1.0f > 0.0f) ? 1.0f : 0.0f;
        s.z = (vz - 1.0f > 0.0f) ? 1.0f : 0.0f;
        s.w = (vw - 1.0f > 0.0f) ? 1.0f : 0.0f;

        vx = vx - s.x * vx;
        vy = vy - s.y * vy;
        vz = vz - s.z * vz;
        vw = vw - s.w * vw;

        // streaming store: output (210 MB) has no reuse, evict-first in L2
        __stcs(o + (size_t)t * N_VEC, s);
    }
}

extern "C" void kernel_launch(void* const* d_in, const int* in_sizes, int n_in,
                              void* d_out, int out_size) {
    const float* in = (const float*)d_in[0];
    float* out = (float*)d_out;

    lif_encoder_kernel<<<2 * BLOCKS_PER_HALF, 256>>>(in, out);
}